// round 10
// baseline (speedup 1.0000x reference)
#include <cuda_runtime.h>
#include <math.h>

typedef unsigned long long u64;

#define NN   32768
#define EE   262144
#define FF   64
#define ZZ   10
#define NBB  8
#define LL   2
#define HH   16

#define NODE1_BLKS 2058            // ceil((NN + ZZ*16)/16)
#define PERMN (NODE1_BLKS * 16)

#define EPSC   0.24253562503633297f
#define SQRT2C 1.4142135623730951f
#define PI_F   3.14159265358979323846f

// Scratch (device globals; allocation-free)
__device__ __align__(16) float g_sA[NN * FF];
__device__ __align__(16) float g_vA[NN * 3 * FF];
__device__ __align__(16) float g_sB[NN * FF];
__device__ __align__(16) float g_vB[NN * 3 * FF];
__device__ __align__(16) float g_aggS[NN * FF];
__device__ __align__(16) float g_aggV[NN * 3 * FF];
__device__ int g_cnt[ZZ];
__device__ int g_pos[ZZ];
__device__ int g_start[ZZ];
__device__ int g_perm[PERMN];

// ---------------- f32x2 helpers ----------------
__device__ __forceinline__ u64 pk2(float lo, float hi) {
    u64 r; asm("mov.b64 %0, {%1, %2};" : "=l"(r) : "f"(lo), "f"(hi)); return r;
}
__device__ __forceinline__ void upk2(u64 v, float& lo, float& hi) {
    asm("mov.b64 {%0, %1}, %2;" : "=f"(lo), "=f"(hi) : "l"(v));
}
__device__ __forceinline__ u64 fma2(u64 a, u64 b, u64 c) {
    u64 r; asm("fma.rn.f32x2 %0, %1, %2, %3;" : "=l"(r) : "l"(a), "l"(b), "l"(c)); return r;
}
__device__ __forceinline__ void redAdd1(float* p, float v) {
    asm volatile("red.global.add.f32 [%0], %1;" :: "l"(p), "f"(v) : "memory");
}

// ---------------------------------------------------------------------------
// Init: s = embed_s[spec], v = 0, agg = 0
// ---------------------------------------------------------------------------
__global__ void initK(const float* __restrict__ embed, const int* __restrict__ spec) {
    int i = blockIdx.x * 256 + threadIdx.x;
    if (i >= NN * FF / 4) return;
    int n = i >> 4, f4 = i & 15;
    ((float4*)g_sA)[i] = ((const float4*)embed)[spec[n] * 16 + f4];
    float4 z = make_float4(0.f, 0.f, 0.f, 0.f);
    ((float4*)g_aggS)[i] = z;
#pragma unroll
    for (int k = 0; k < 3; k++) {
        ((float4*)g_vA)[(n * 3 + k) * 16 + f4]   = z;
        ((float4*)g_aggV)[(n * 3 + k) * 16 + f4] = z;
    }
}

// ---------------- species permutation build (blocks of 16 uniform species) --
__global__ void fillK() {
    int i = blockIdx.x * 256 + threadIdx.x;
    if (i < PERMN) g_perm[i] = 0;
    if (i < ZZ) g_cnt[i] = 0;
}
__global__ void histK(const int* __restrict__ spec) {
    int n = blockIdx.x * 256 + threadIdx.x;
    if (n < NN) atomicAdd(&g_cnt[spec[n]], 1);
}
__global__ void offK() {
    if (threadIdx.x == 0) {
        int acc = 0;
        for (int z = 0; z < ZZ; z++) {
            g_start[z] = acc; g_pos[z] = acc;
            acc += ((g_cnt[z] + 15) >> 4) << 4;
        }
    }
}
__global__ void scatK(const int* __restrict__ spec) {
    int n = blockIdx.x * 256 + threadIdx.x;
    if (n < NN) g_perm[atomicAdd(&g_pos[spec[n]], 1)] = n;
}
__global__ void padK() {
    int t = threadIdx.x;
    if (t >= ZZ * 16) return;
    int z = t >> 4, i = t & 15;
    int st = g_start[z], c = g_cnt[z];
    int seg = ((c + 15) >> 4) << 4;
    if (i < seg - c) g_perm[st + c + i] = g_perm[st];
}

// ---------------------------------------------------------------------------
// Per-edge scalar staging
// ---------------------------------------------------------------------------
__device__ __forceinline__ void stageEdge(
        float (*rb)[32], float (*yv)[32], int* sS, int* rS,
        const float* __restrict__ vec,
        const int* __restrict__ snd, const int* __restrict__ rcv,
        int e, int lane) {
    sS[lane] = snd[e];
    rS[lane] = rcv[e];
    float vx = vec[e * 3 + 0], vy = vec[e * 3 + 1], vz = vec[e * 3 + 2];
    float r  = sqrtf(vx * vx + vy * vy + vz * vz + 1e-12f);
    float rc = fmaxf(r, 1e-6f);
    float env = 0.f;
    if (r < 1.f) {
        float r2 = r * r, r6 = r2 * r2 * r2;
        env = 1.f - 28.f * r6 + 48.f * r6 * r - 21.f * r6 * r2;
    }
    float scale = SQRT2C * env / rc;
    float s1, c1;
    __sincosf(PI_F * rc, &s1, &c1);
    float c2 = 2.f * c1, sp = s1, spp = 0.f;
    rb[0][lane] = s1 * scale;
#pragma unroll
    for (int n = 1; n < NBB; n++) {
        float sn = c2 * sp - spp;
        rb[n][lane] = sn * scale;
        spp = sp; sp = sn;
    }
    float iy = 1.f / r;
    yv[0][lane] = vx * iy; yv[1][lane] = vy * iy; yv[2][lane] = vz * iy;
}

// ---------------------------------------------------------------------------
// Edge kernel (round-7 proven): 256 threads = 64 channels x 4 edge-lanes,
// Wr slice in registers, per-edge scalars double-buffered in smem.
// ---------------------------------------------------------------------------
template <bool FIRST>
__global__ void __launch_bounds__(256) edgeK(
                      const float* __restrict__ vec,
                      const float* __restrict__ WrL,
                      const int*   __restrict__ snd,
                      const int*   __restrict__ rcv,
                      const float* __restrict__ sIn,
                      const float* __restrict__ vIn) {
    const int NP = FIRST ? 2 : 5;
    __shared__ float rbS[2][NBB][32];
    __shared__ float yS[2][3][32];
    __shared__ int   sndS[2][32];
    __shared__ int   rcvS[2][32];

    int t = threadIdx.x, f = t & 63, el = t >> 6;

    float wreg[NBB][FIRST ? 2 : 5];
#pragma unroll
    for (int n = 0; n < NBB; n++)
#pragma unroll
        for (int pi = 0; pi < NP; pi++) {
            int p = FIRST ? pi * 2 : pi;
            wreg[n][pi] = WrL[n * 320 + p * 64 + f];
        }

    int base = blockIdx.x * 128;
    if (t < 32)
        stageEdge(rbS[0], yS[0], sndS[0], rcvS[0], vec, snd, rcv, base + t, t);
    __syncthreads();

#pragma unroll
    for (int s = 0; s < 4; s++) {
        int buf = s & 1;
        if (s < 3 && t < 32)
            stageEdge(rbS[buf ^ 1], yS[buf ^ 1], sndS[buf ^ 1], rcvS[buf ^ 1],
                      vec, snd, rcv, base + (s + 1) * 32 + t, t);

        int e0 = el * 8;
#pragma unroll 2
        for (int le = 0; le < 8; le++) {
            int li = e0 + le;
            int s_ = sndS[buf][li];
            int r_ = rcvS[buf][li];

            float w[5];
#pragma unroll
            for (int pi = 0; pi < NP; pi++) w[pi] = 0.f;
#pragma unroll
            for (int n = 0; n < NBB; n++) {
                float rn = rbS[buf][n][li];
#pragma unroll
                for (int pi = 0; pi < NP; pi++)
                    w[pi] = fmaf(rn, wreg[n][pi], w[pi]);
            }

            float y0 = yS[buf][0][li], y1 = yS[buf][1][li], y2 = yS[buf][2][li];
            float ss = sIn[s_ * FF + f];

            float m0, m1x, m1y, m1z;
            if (FIRST) {
                m0 = w[0] * ss;
                float cc = w[1] * ss;
                m1x = cc * y0; m1y = cc * y1; m1z = cc * y2;
            } else {
                float vsx = vIn[(s_ * 3 + 0) * FF + f];
                float vsy = vIn[(s_ * 3 + 1) * FF + f];
                float vsz = vIn[(s_ * 3 + 2) * FF + f];
                float dot = vsx * y0 + vsy * y1 + vsz * y2;
                m0 = w[0] * ss + w[1] * dot;
                float cc = w[2] * ss;
                m1x = cc * y0 + w[3] * vsx + w[4] * (vsy * y2 - vsz * y1);
                m1y = cc * y1 + w[3] * vsy + w[4] * (vsz * y0 - vsx * y2);
                m1z = cc * y2 + w[3] * vsz + w[4] * (vsx * y1 - vsy * y0);
            }

            redAdd1(&g_aggS[r_ * FF + f], m0);
            redAdd1(&g_aggV[(r_ * 3 + 0) * FF + f], m1x);
            redAdd1(&g_aggV[(r_ * 3 + 1) * FF + f], m1y);
            redAdd1(&g_aggV[(r_ * 3 + 2) * FF + f], m1z);
        }
        __syncthreads();
    }
}

// ---------------------------------------------------------------------------
// Node kernel v2: f32x2 GEMMs, 16 nodes/block x 16 threads/node (4 ch each).
// One 32KB weight buffer reloaded for each GEMM stage. Layer 1 runs on a
// species-uniform permutation so skip weights stage once per block.
// ---------------------------------------------------------------------------
template <int LAYER>
__global__ void __launch_bounds__(256) nodeK(
                      const float* __restrict__ sOld,
                      const float* __restrict__ vOld,
                      float* __restrict__ sNew,
                      float* __restrict__ vNew,
                      const int*   __restrict__ spec,
                      const float* __restrict__ WlsL,
                      const float* __restrict__ WlvL,
                      const float* __restrict__ pwL,
                      const float* __restrict__ WpsL,
                      const float* __restrict__ WpvL,
                      const float* __restrict__ skipS,
                      const float* __restrict__ skipV,
                      const float* __restrict__ Wread0,
                      const float* __restrict__ Wr1a,
                      const float* __restrict__ Wr1b,
                      float* __restrict__ out) {
    extern __shared__ float sm[];
    float* Wb0 = sm;                         // 4096
    float* Wb1 = sm + 4096;                  // 4096
    u64*   A2s = (u64*)(sm + 8192);          // [16][64]
    u64*   A2v = (u64*)(sm + 10240);         // [16][3][64]
    u64*   B2s = (u64*)(sm + 16384);         // [16][64]   (layer 1)
    u64*   B2v = (u64*)(sm + 18432);         // [16][3][64]

    int t  = threadIdx.x;
    int nl = t >> 4;
    int fi = t & 15;
    int c0 = fi * 4;
    int n  = (LAYER == 0) ? (blockIdx.x * 16 + nl) : g_perm[blockIdx.x * 16 + nl];

    // Stage 0: Wls/Wlv + packed A (agg*EPS) (+ packed B = old features)
    {
        const float4* a4 = (const float4*)WlsL;
        const float4* b4 = (const float4*)WlvL;
        for (int i = t; i < 1024; i += 256) {
            ((float4*)Wb0)[i] = a4[i];
            ((float4*)Wb1)[i] = b4[i];
        }
    }
    {
        float4 a = ((const float4*)g_aggS)[n * 16 + fi];
        A2s[nl * 64 + c0 + 0] = pk2(a.x * EPSC, a.x * EPSC);
        A2s[nl * 64 + c0 + 1] = pk2(a.y * EPSC, a.y * EPSC);
        A2s[nl * 64 + c0 + 2] = pk2(a.z * EPSC, a.z * EPSC);
        A2s[nl * 64 + c0 + 3] = pk2(a.w * EPSC, a.w * EPSC);
#pragma unroll
        for (int k = 0; k < 3; k++) {
            float4 v = ((const float4*)g_aggV)[(n * 3 + k) * 16 + fi];
            u64* dst = &A2v[(nl * 3 + k) * 64 + c0];
            dst[0] = pk2(v.x * EPSC, v.x * EPSC);
            dst[1] = pk2(v.y * EPSC, v.y * EPSC);
            dst[2] = pk2(v.z * EPSC, v.z * EPSC);
            dst[3] = pk2(v.w * EPSC, v.w * EPSC);
        }
        if (LAYER == 0) {
            float4 z = make_float4(0.f, 0.f, 0.f, 0.f);
            ((float4*)g_aggS)[n * 16 + fi] = z;
#pragma unroll
            for (int k = 0; k < 3; k++) ((float4*)g_aggV)[(n * 3 + k) * 16 + fi] = z;
        }
        if (LAYER > 0) {
            float4 b = ((const float4*)sOld)[n * 16 + fi];
            B2s[nl * 64 + c0 + 0] = pk2(b.x, b.x);
            B2s[nl * 64 + c0 + 1] = pk2(b.y, b.y);
            B2s[nl * 64 + c0 + 2] = pk2(b.z, b.z);
            B2s[nl * 64 + c0 + 3] = pk2(b.w, b.w);
#pragma unroll
            for (int k = 0; k < 3; k++) {
                float4 v = ((const float4*)vOld)[(n * 3 + k) * 16 + fi];
                u64* dst = &B2v[(nl * 3 + k) * 64 + c0];
                dst[0] = pk2(v.x, v.x);
                dst[1] = pk2(v.y, v.y);
                dst[2] = pk2(v.z, v.z);
                dst[3] = pk2(v.w, v.w);
            }
        }
    }
    __syncthreads();

    // Phase 1: s2 = aggS@Wls, v2 = aggV@Wlv  (f32x2, 4 channels/thread)
    u64 s2a = 0, s2b = 0, vxa = 0, vxb = 0, vya = 0, vyb = 0, vza = 0, vzb = 0;
#pragma unroll 8
    for (int j = 0; j < FF; j++) {
        u64 as = A2s[nl * 64 + j];
        u64 ax = A2v[(nl * 3 + 0) * 64 + j];
        u64 ay = A2v[(nl * 3 + 1) * 64 + j];
        u64 az = A2v[(nl * 3 + 2) * 64 + j];
        float4 w0 = *(const float4*)&Wb0[j * 64 + c0];
        float4 w1 = *(const float4*)&Wb1[j * 64 + c0];
        u64 w0a = pk2(w0.x, w0.y), w0b = pk2(w0.z, w0.w);
        u64 w1a = pk2(w1.x, w1.y), w1b = pk2(w1.z, w1.w);
        s2a = fma2(as, w0a, s2a); s2b = fma2(as, w0b, s2b);
        vxa = fma2(ax, w1a, vxa); vxb = fma2(ax, w1b, vxb);
        vya = fma2(ay, w1a, vya); vyb = fma2(ay, w1b, vyb);
        vza = fma2(az, w1a, vza); vzb = fma2(az, w1b, vzb);
    }

    int z = spec[n];

    // Skip GEMM (layer 1): stage skip weights once per (species-uniform) block
    u64 sca = 0, scb = 0, sxa = 0, sxb = 0, sya = 0, syb = 0, sza = 0, szb = 0;
    if (LAYER > 0) {
        __syncthreads();
        {
            const float4* a4 = (const float4*)(skipS + z * FF * FF);
            const float4* b4 = (const float4*)(skipV + z * FF * FF);
            for (int i = t; i < 1024; i += 256) {
                ((float4*)Wb0)[i] = a4[i];
                ((float4*)Wb1)[i] = b4[i];
            }
        }
        __syncthreads();
#pragma unroll 8
        for (int j = 0; j < FF; j++) {
            u64 bs = B2s[nl * 64 + j];
            u64 bx = B2v[(nl * 3 + 0) * 64 + j];
            u64 by = B2v[(nl * 3 + 1) * 64 + j];
            u64 bz = B2v[(nl * 3 + 2) * 64 + j];
            float4 w0 = *(const float4*)&Wb0[j * 64 + c0];
            float4 w1 = *(const float4*)&Wb1[j * 64 + c0];
            u64 w0a = pk2(w0.x, w0.y), w0b = pk2(w0.z, w0.w);
            u64 w1a = pk2(w1.x, w1.y), w1b = pk2(w1.z, w1.w);
            sca = fma2(bs, w0a, sca); scb = fma2(bs, w0b, scb);
            sxa = fma2(bx, w1a, sxa); sxb = fma2(bx, w1b, sxb);
            sya = fma2(by, w1a, sya); syb = fma2(by, w1b, syb);
            sza = fma2(bz, w1a, sza); szb = fma2(bz, w1b, szb);
        }
    }

    // Product basis (per channel scalar)
    float S[4], VX[4], VY[4], VZ[4];
    upk2(s2a, S[0], S[1]);  upk2(s2b, S[2], S[3]);
    upk2(vxa, VX[0], VX[1]); upk2(vxb, VX[2], VX[3]);
    upk2(vya, VY[0], VY[1]); upk2(vyb, VY[2], VY[3]);
    upk2(vza, VZ[0], VZ[1]); upk2(vzb, VZ[2], VZ[3]);

    const float* pp = pwL + z * 9 * FF;
    float4 P[9];
#pragma unroll
    for (int k = 0; k < 9; k++) P[k] = *(const float4*)&pp[k * FF + c0];

    float PS[4], PVX[4], PVY[4], PVZ[4];
#pragma unroll
    for (int c = 0; c < 4; c++) {
        float s1 = S[c];
        float vv = VX[c] * VX[c] + VY[c] * VY[c] + VZ[c] * VZ[c];
        float s2q = s1 * s1;
        PS[c] = (&P[0].x)[c] * s1 + (&P[1].x)[c] * s2q + (&P[2].x)[c] * vv
              + (&P[3].x)[c] * s2q * s1 + (&P[4].x)[c] * s1 * vv;
        float pf = (&P[5].x)[c] + (&P[6].x)[c] * s1 + (&P[7].x)[c] * s2q + (&P[8].x)[c] * vv;
        PVX[c] = pf * VX[c]; PVY[c] = pf * VY[c]; PVZ[c] = pf * VZ[c];
    }
    __syncthreads();

    // Overwrite A2 with product basis; reload Wb with Wps/Wpv
    {
#pragma unroll
        for (int c = 0; c < 4; c++) {
            A2s[nl * 64 + c0 + c] = pk2(PS[c], PS[c]);
            A2v[(nl * 3 + 0) * 64 + c0 + c] = pk2(PVX[c], PVX[c]);
            A2v[(nl * 3 + 1) * 64 + c0 + c] = pk2(PVY[c], PVY[c]);
            A2v[(nl * 3 + 2) * 64 + c0 + c] = pk2(PVZ[c], PVZ[c]);
        }
        const float4* a4 = (const float4*)WpsL;
        const float4* b4 = (const float4*)WpvL;
        for (int i = t; i < 1024; i += 256) {
            ((float4*)Wb0)[i] = a4[i];
            ((float4*)Wb1)[i] = b4[i];
        }
    }
    __syncthreads();

    // Phase 2: sN = ps@Wps (+skip), vN = pv@Wpv (+skip)
#pragma unroll 8
    for (int j = 0; j < FF; j++) {
        u64 as = A2s[nl * 64 + j];
        u64 ax = A2v[(nl * 3 + 0) * 64 + j];
        u64 ay = A2v[(nl * 3 + 1) * 64 + j];
        u64 az = A2v[(nl * 3 + 2) * 64 + j];
        float4 w0 = *(const float4*)&Wb0[j * 64 + c0];
        float4 w1 = *(const float4*)&Wb1[j * 64 + c0];
        u64 w0a = pk2(w0.x, w0.y), w0b = pk2(w0.z, w0.w);
        u64 w1a = pk2(w1.x, w1.y), w1b = pk2(w1.z, w1.w);
        sca = fma2(as, w0a, sca); scb = fma2(as, w0b, scb);
        sxa = fma2(ax, w1a, sxa); sxb = fma2(ax, w1b, sxb);
        sya = fma2(ay, w1a, sya); syb = fma2(ay, w1b, syb);
        sza = fma2(az, w1a, sza); szb = fma2(az, w1b, szb);
    }

    float SN[4];
    upk2(sca, SN[0], SN[1]); upk2(scb, SN[2], SN[3]);

    if (LAYER < LL - 1) {
        float v0, v1, v2, v3;
        ((float4*)sNew)[n * 16 + fi] = make_float4(SN[0], SN[1], SN[2], SN[3]);
        upk2(sxa, v0, v1); upk2(sxb, v2, v3);
        ((float4*)vNew)[(n * 3 + 0) * 16 + fi] = make_float4(v0, v1, v2, v3);
        upk2(sya, v0, v1); upk2(syb, v2, v3);
        ((float4*)vNew)[(n * 3 + 1) * 16 + fi] = make_float4(v0, v1, v2, v3);
        upk2(sza, v0, v1); upk2(szb, v2, v3);
        ((float4*)vNew)[(n * 3 + 2) * 16 + fi] = make_float4(v0, v1, v2, v3);
    }

    if (LAYER == 0) {
        float4 wr = *(const float4*)&Wread0[c0];
        float part = SN[0] * wr.x + SN[1] * wr.y + SN[2] * wr.z + SN[3] * wr.w;
#pragma unroll
        for (int o = 8; o > 0; o >>= 1)
            part += __shfl_xor_sync(0xffffffffu, part, o);
        if (fi == 0) out[n * LL + 0] = part;
    } else {
        // stage sN as floats (reuse B2s region), then MLP readout
        float* sNs = (float*)B2s;
        __syncthreads();
        *(float4*)&sNs[nl * 64 + c0] = make_float4(SN[0], SN[1], SN[2], SN[3]);
        __syncthreads();
        float a = 0.f;
#pragma unroll 8
        for (int g = 0; g < FF; g++)
            a = fmaf(sNs[nl * 64 + g], Wr1a[g * HH + fi], a);
        float sil = a / (1.f + __expf(-a));
        float part = sil * Wr1b[fi];
#pragma unroll
        for (int o = 8; o > 0; o >>= 1)
            part += __shfl_xor_sync(0xffffffffu, part, o);
        if (fi == 0) out[n * LL + (LL - 1)] = part;
    }
}

// ---------------------------------------------------------------------------
extern "C" void kernel_launch(void* const* d_in, const int* in_sizes, int n_in,
                              void* d_out, int out_size) {
    const float* vectors = (const float*)d_in[0];
    const float* embed_s = (const float*)d_in[1];
    const float* Wr      = (const float*)d_in[2];
    const float* Wls     = (const float*)d_in[3];
    const float* Wlv     = (const float*)d_in[4];
    const float* skip_s  = (const float*)d_in[5];
    const float* skip_v  = (const float*)d_in[6];
    const float* pw      = (const float*)d_in[7];
    const float* Wps     = (const float*)d_in[8];
    const float* Wpv     = (const float*)d_in[9];
    const float* Wread0  = (const float*)d_in[10];
    const float* Wr1a    = (const float*)d_in[11];
    const float* Wr1b    = (const float*)d_in[12];
    const int*   senders   = (const int*)d_in[13];
    const int*   receivers = (const int*)d_in[14];
    const int*   species   = (const int*)d_in[15];
    float* out = (float*)d_out;

    void *p_sA, *p_vA, *p_sB, *p_vB;
    cudaGetSymbolAddress(&p_sA, g_sA);
    cudaGetSymbolAddress(&p_vA, g_vA);
    cudaGetSymbolAddress(&p_sB, g_sB);
    cudaGetSymbolAddress(&p_vB, g_vB);
    float* sA = (float*)p_sA;
    float* vA = (float*)p_vA;
    float* sB = (float*)p_sB;
    float* vB = (float*)p_vB;

    const int NODE0_SMEM = 16384 * 4;   // 64KB
    const int NODE1_SMEM = 24576 * 4;   // 96KB
    static bool attrSet = false;
    if (!attrSet) {
        cudaFuncSetAttribute(nodeK<0>, cudaFuncAttributeMaxDynamicSharedMemorySize, NODE0_SMEM);
        cudaFuncSetAttribute(nodeK<1>, cudaFuncAttributeMaxDynamicSharedMemorySize, NODE1_SMEM);
        attrSet = true;
    }

    initK<<<(NN * FF / 4 + 255) / 256, 256>>>(embed_s, species);

    // species-uniform permutation for layer-1 node kernel
    fillK<<<(PERMN + 255) / 256, 256>>>();
    histK<<<NN / 256, 256>>>(species);
    offK<<<1, 32>>>();
    scatK<<<NN / 256, 256>>>(species);
    padK<<<1, 256>>>();

    // ---- Layer 0 ----
    edgeK<true><<<EE / 128, 256>>>(vectors, Wr, senders, receivers, sA, vA);
    nodeK<0><<<NN / 16, 256, NODE0_SMEM>>>(sA, vA, sB, vB, species,
                              Wls, Wlv, pw, Wps, Wpv,
                              skip_s, skip_v, Wread0, Wr1a, Wr1b, out);

    // ---- Layer 1 ----
    edgeK<false><<<EE / 128, 256>>>(vectors, Wr + NBB * 5 * FF, senders, receivers, sB, vB);
    nodeK<1><<<NODE1_BLKS, 256, NODE1_SMEM>>>(sB, vB, sA, vA, species,
                              Wls + FF * FF, Wlv + FF * FF,
                              pw + ZZ * 9 * FF,
                              Wps + FF * FF, Wpv + FF * FF,
                              skip_s, skip_v, Wread0, Wr1a, Wr1b, out);
}

// round 11
// speedup vs baseline: 1.2064x; 1.2064x over previous
#include <cuda_runtime.h>
#include <math.h>

#define NN   32768
#define EE   262144
#define FF   64
#define ZZ   10
#define NBB  8
#define LL   2
#define HH   16

#define EPSC   0.24253562503633297f
#define SQRT2C 1.4142135623730951f
#define PI_F   3.14159265358979323846f

// Scratch (device globals; allocation-free)
__device__ __align__(16) float g_sA[NN * FF];
__device__ __align__(16) float g_vA[NN * 3 * FF];
__device__ __align__(16) float g_sB[NN * FF];
__device__ __align__(16) float g_vB[NN * 3 * FF];
__device__ __align__(16) float g_aggS[NN * FF];
__device__ __align__(16) float g_aggV[NN * 3 * FF];

__device__ __forceinline__ void redAdd1(float* p, float v) {
    asm volatile("red.global.add.f32 [%0], %1;" :: "l"(p), "f"(v) : "memory");
}

// ---------------------------------------------------------------------------
// Init: s = embed_s[spec], v = 0, agg = 0
// ---------------------------------------------------------------------------
__global__ void initK(const float* __restrict__ embed, const int* __restrict__ spec) {
    int i = blockIdx.x * 256 + threadIdx.x;
    if (i >= NN * FF / 4) return;
    int n = i >> 4, f4 = i & 15;
    ((float4*)g_sA)[i] = ((const float4*)embed)[spec[n] * 16 + f4];
    float4 z = make_float4(0.f, 0.f, 0.f, 0.f);
    ((float4*)g_aggS)[i] = z;
#pragma unroll
    for (int k = 0; k < 3; k++) {
        ((float4*)g_vA)[(n * 3 + k) * 16 + f4]   = z;
        ((float4*)g_aggV)[(n * 3 + k) * 16 + f4] = z;
    }
}

// ---------------------------------------------------------------------------
// Per-edge scalar staging (round-7 proven)
// ---------------------------------------------------------------------------
__device__ __forceinline__ void stageEdge(
        float (*rb)[32], float (*yv)[32], int* sS, int* rS,
        const float* __restrict__ vec,
        const int* __restrict__ snd, const int* __restrict__ rcv,
        int e, int lane) {
    sS[lane] = snd[e];
    rS[lane] = rcv[e];
    float vx = vec[e * 3 + 0], vy = vec[e * 3 + 1], vz = vec[e * 3 + 2];
    float r  = sqrtf(vx * vx + vy * vy + vz * vz + 1e-12f);
    float rc = fmaxf(r, 1e-6f);
    float env = 0.f;
    if (r < 1.f) {
        float r2 = r * r, r6 = r2 * r2 * r2;
        env = 1.f - 28.f * r6 + 48.f * r6 * r - 21.f * r6 * r2;
    }
    float scale = SQRT2C * env / rc;
    float s1, c1;
    __sincosf(PI_F * rc, &s1, &c1);
    float c2 = 2.f * c1, sp = s1, spp = 0.f;
    rb[0][lane] = s1 * scale;
#pragma unroll
    for (int n = 1; n < NBB; n++) {
        float sn = c2 * sp - spp;
        rb[n][lane] = sn * scale;
        spp = sp; sp = sn;
    }
    float iy = 1.f / r;
    yv[0][lane] = vx * iy; yv[1][lane] = vy * iy; yv[2][lane] = vz * iy;
}

// ---------------------------------------------------------------------------
// Edge kernel (round-7 proven)
// ---------------------------------------------------------------------------
template <bool FIRST>
__global__ void __launch_bounds__(256) edgeK(
                      const float* __restrict__ vec,
                      const float* __restrict__ WrL,
                      const int*   __restrict__ snd,
                      const int*   __restrict__ rcv,
                      const float* __restrict__ sIn,
                      const float* __restrict__ vIn) {
    const int NP = FIRST ? 2 : 5;
    __shared__ float rbS[2][NBB][32];
    __shared__ float yS[2][3][32];
    __shared__ int   sndS[2][32];
    __shared__ int   rcvS[2][32];

    int t = threadIdx.x, f = t & 63, el = t >> 6;

    float wreg[NBB][FIRST ? 2 : 5];
#pragma unroll
    for (int n = 0; n < NBB; n++)
#pragma unroll
        for (int pi = 0; pi < NP; pi++) {
            int p = FIRST ? pi * 2 : pi;
            wreg[n][pi] = WrL[n * 320 + p * 64 + f];
        }

    int base = blockIdx.x * 128;
    if (t < 32)
        stageEdge(rbS[0], yS[0], sndS[0], rcvS[0], vec, snd, rcv, base + t, t);
    __syncthreads();

#pragma unroll
    for (int s = 0; s < 4; s++) {
        int buf = s & 1;
        if (s < 3 && t < 32)
            stageEdge(rbS[buf ^ 1], yS[buf ^ 1], sndS[buf ^ 1], rcvS[buf ^ 1],
                      vec, snd, rcv, base + (s + 1) * 32 + t, t);

        int e0 = el * 8;
#pragma unroll 2
        for (int le = 0; le < 8; le++) {
            int li = e0 + le;
            int s_ = sndS[buf][li];
            int r_ = rcvS[buf][li];

            float w[5];
#pragma unroll
            for (int pi = 0; pi < NP; pi++) w[pi] = 0.f;
#pragma unroll
            for (int n = 0; n < NBB; n++) {
                float rn = rbS[buf][n][li];
#pragma unroll
                for (int pi = 0; pi < NP; pi++)
                    w[pi] = fmaf(rn, wreg[n][pi], w[pi]);
            }

            float y0 = yS[buf][0][li], y1 = yS[buf][1][li], y2 = yS[buf][2][li];
            float ss = sIn[s_ * FF + f];

            float m0, m1x, m1y, m1z;
            if (FIRST) {
                m0 = w[0] * ss;
                float cc = w[1] * ss;
                m1x = cc * y0; m1y = cc * y1; m1z = cc * y2;
            } else {
                float vsx = vIn[(s_ * 3 + 0) * FF + f];
                float vsy = vIn[(s_ * 3 + 1) * FF + f];
                float vsz = vIn[(s_ * 3 + 2) * FF + f];
                float dot = vsx * y0 + vsy * y1 + vsz * y2;
                m0 = w[0] * ss + w[1] * dot;
                float cc = w[2] * ss;
                m1x = cc * y0 + w[3] * vsx + w[4] * (vsy * y2 - vsz * y1);
                m1y = cc * y1 + w[3] * vsy + w[4] * (vsz * y0 - vsx * y2);
                m1z = cc * y2 + w[3] * vsz + w[4] * (vsx * y1 - vsy * y0);
            }

            redAdd1(&g_aggS[r_ * FF + f], m0);
            redAdd1(&g_aggV[(r_ * 3 + 0) * FF + f], m1x);
            redAdd1(&g_aggV[(r_ * 3 + 1) * FF + f], m1y);
            redAdd1(&g_aggV[(r_ * 3 + 2) * FF + f], m1z);
        }
        __syncthreads();
    }
}

// ---------------------------------------------------------------------------
// Node kernel v3: 4-node x 2-channel register tiles.
// 256 threads = 8 slots x 32 fi; each slot owns 4 nodes -> 32 nodes/block.
// Per j, one float2 weight load per matrix feeds 4 nodes (weight-LDS /4).
// Smem floats: Wb0[4096] Wb1[4096] As[2048] Av[6144] (| Bs[2048] Bv[6144] L1)
// ---------------------------------------------------------------------------
template <int LAYER>
__global__ void __launch_bounds__(256) nodeK(
                      const float* __restrict__ sOld,
                      const float* __restrict__ vOld,
                      float* __restrict__ sNew,
                      float* __restrict__ vNew,
                      const int*   __restrict__ spec,
                      const float* __restrict__ WlsL,
                      const float* __restrict__ WlvL,
                      const float* __restrict__ pwL,
                      const float* __restrict__ WpsL,
                      const float* __restrict__ WpvL,
                      const float* __restrict__ skipS,
                      const float* __restrict__ skipV,
                      const float* __restrict__ Wread0,
                      const float* __restrict__ Wr1a,
                      const float* __restrict__ Wr1b,
                      float* __restrict__ out) {
    extern __shared__ float sm[];
    float* Wb0 = sm;                 // 4096
    float* Wb1 = sm + 4096;          // 4096
    float* As  = sm + 8192;          // 32*64  = 2048
    float* Av  = sm + 10240;         // 32*192 = 6144
    float* Bs  = sm + 16384;         // layer1: 2048
    float* Bv  = sm + 18432;         // layer1: 6144

    int t    = threadIdx.x;
    int fi   = t & 31;
    int slot = t >> 5;
    int c0   = fi * 2;
    int nb   = blockIdx.x * 32 + slot * 4;

    // Stage 0: Wls/Wlv + agg rows (+old rows layer1)
    {
        const float4* a4 = (const float4*)WlsL;
        const float4* b4 = (const float4*)WlvL;
        for (int i = t; i < 1024; i += 256) {
            ((float4*)Wb0)[i] = a4[i];
            ((float4*)Wb1)[i] = b4[i];
        }
    }
#pragma unroll
    for (int u = 0; u < 4; u++) {
        int n = nb + u, ln = slot * 4 + u;
        float2 a = *(const float2*)&g_aggS[n * 64 + c0];
        *(float2*)&As[ln * 64 + c0] = make_float2(a.x * EPSC, a.y * EPSC);
#pragma unroll
        for (int k = 0; k < 3; k++) {
            float2 v = *(const float2*)&g_aggV[(n * 3 + k) * 64 + c0];
            *(float2*)&Av[(ln * 3 + k) * 64 + c0] = make_float2(v.x * EPSC, v.y * EPSC);
        }
        if (LAYER == 0) {
            *(float2*)&g_aggS[n * 64 + c0] = make_float2(0.f, 0.f);
#pragma unroll
            for (int k = 0; k < 3; k++)
                *(float2*)&g_aggV[(n * 3 + k) * 64 + c0] = make_float2(0.f, 0.f);
        }
        if (LAYER > 0) {
            *(float2*)&Bs[ln * 64 + c0] = *(const float2*)&sOld[n * 64 + c0];
#pragma unroll
            for (int k = 0; k < 3; k++)
                *(float2*)&Bv[(ln * 3 + k) * 64 + c0] =
                    *(const float2*)&vOld[(n * 3 + k) * 64 + c0];
        }
    }
    __syncthreads();

    // Phase 1: s2 = aggS@Wls, v2 = aggV@Wlv   (4 nodes x 2 ch per thread)
    float aS[4][2], aX[4][2], aY[4][2], aZ[4][2];
#pragma unroll
    for (int u = 0; u < 4; u++)
#pragma unroll
        for (int c = 0; c < 2; c++) { aS[u][c] = 0.f; aX[u][c] = 0.f; aY[u][c] = 0.f; aZ[u][c] = 0.f; }

#pragma unroll 4
    for (int j = 0; j < FF; j++) {
        float2 w0 = *(const float2*)&Wb0[j * 64 + c0];
        float2 w1 = *(const float2*)&Wb1[j * 64 + c0];
#pragma unroll
        for (int u = 0; u < 4; u++) {
            int ln = slot * 4 + u;
            float a  = As[ln * 64 + j];
            float ax = Av[(ln * 3 + 0) * 64 + j];
            float ay = Av[(ln * 3 + 1) * 64 + j];
            float az = Av[(ln * 3 + 2) * 64 + j];
            aS[u][0] = fmaf(a,  w0.x, aS[u][0]); aS[u][1] = fmaf(a,  w0.y, aS[u][1]);
            aX[u][0] = fmaf(ax, w1.x, aX[u][0]); aX[u][1] = fmaf(ax, w1.y, aX[u][1]);
            aY[u][0] = fmaf(ay, w1.x, aY[u][0]); aY[u][1] = fmaf(ay, w1.y, aY[u][1]);
            aZ[u][0] = fmaf(az, w1.x, aZ[u][0]); aZ[u][1] = fmaf(az, w1.y, aZ[u][1]);
        }
    }

    int zs[4];
#pragma unroll
    for (int u = 0; u < 4; u++) zs[u] = spec[nb + u];

    // Product basis per node/channel
    float PS[4][2], PX[4][2], PY[4][2], PZ[4][2];
#pragma unroll
    for (int u = 0; u < 4; u++) {
        const float* pp = pwL + zs[u] * 9 * FF;
#pragma unroll
        for (int c = 0; c < 2; c++) {
            float s1 = aS[u][c];
            float vx = aX[u][c], vy = aY[u][c], vz = aZ[u][c];
            float vv = vx * vx + vy * vy + vz * vz;
            float s2q = s1 * s1;
            float p0 = pp[0 * FF + c0 + c], p1 = pp[1 * FF + c0 + c], p2 = pp[2 * FF + c0 + c];
            float p3 = pp[3 * FF + c0 + c], p4 = pp[4 * FF + c0 + c], p5 = pp[5 * FF + c0 + c];
            float p6 = pp[6 * FF + c0 + c], p7 = pp[7 * FF + c0 + c], p8 = pp[8 * FF + c0 + c];
            PS[u][c] = p0 * s1 + p1 * s2q + p2 * vv + p3 * s2q * s1 + p4 * s1 * vv;
            float pf = p5 + p6 * s1 + p7 * s2q + p8 * vv;
            PX[u][c] = pf * vx; PY[u][c] = pf * vy; PZ[u][c] = pf * vz;
        }
    }
    __syncthreads();

    // Overwrite As/Av with product basis; reload Wb with Wps/Wpv
#pragma unroll
    for (int u = 0; u < 4; u++) {
        int ln = slot * 4 + u;
        *(float2*)&As[ln * 64 + c0] = make_float2(PS[u][0], PS[u][1]);
        *(float2*)&Av[(ln * 3 + 0) * 64 + c0] = make_float2(PX[u][0], PX[u][1]);
        *(float2*)&Av[(ln * 3 + 1) * 64 + c0] = make_float2(PY[u][0], PY[u][1]);
        *(float2*)&Av[(ln * 3 + 2) * 64 + c0] = make_float2(PZ[u][0], PZ[u][1]);
    }
    {
        const float4* a4 = (const float4*)WpsL;
        const float4* b4 = (const float4*)WpvL;
        for (int i = t; i < 1024; i += 256) {
            ((float4*)Wb0)[i] = a4[i];
            ((float4*)Wb1)[i] = b4[i];
        }
    }
    __syncthreads();

    // Re-init accumulators: layer0 -> 0; layer1 -> skip GEMM
#pragma unroll
    for (int u = 0; u < 4; u++)
#pragma unroll
        for (int c = 0; c < 2; c++) { aS[u][c] = 0.f; aX[u][c] = 0.f; aY[u][c] = 0.f; aZ[u][c] = 0.f; }

    if (LAYER > 0) {
#pragma unroll 2
        for (int j = 0; j < FF; j++) {
#pragma unroll
            for (int u = 0; u < 4; u++) {
                int ln = slot * 4 + u;
                const float* SsW = skipS + zs[u] * FF * FF + j * 64 + c0;
                const float* SvW = skipV + zs[u] * FF * FF + j * 64 + c0;
                float2 w0 = *(const float2*)SsW;
                float2 w1 = *(const float2*)SvW;
                float b  = Bs[ln * 64 + j];
                float bx = Bv[(ln * 3 + 0) * 64 + j];
                float by = Bv[(ln * 3 + 1) * 64 + j];
                float bz = Bv[(ln * 3 + 2) * 64 + j];
                aS[u][0] = fmaf(b,  w0.x, aS[u][0]); aS[u][1] = fmaf(b,  w0.y, aS[u][1]);
                aX[u][0] = fmaf(bx, w1.x, aX[u][0]); aX[u][1] = fmaf(bx, w1.y, aX[u][1]);
                aY[u][0] = fmaf(by, w1.x, aY[u][0]); aY[u][1] = fmaf(by, w1.y, aY[u][1]);
                aZ[u][0] = fmaf(bz, w1.x, aZ[u][0]); aZ[u][1] = fmaf(bz, w1.y, aZ[u][1]);
            }
        }
    }

    // Phase 2: sN = ps@Wps (+skip), vN = pv@Wpv (+skip)
#pragma unroll 4
    for (int j = 0; j < FF; j++) {
        float2 w0 = *(const float2*)&Wb0[j * 64 + c0];
        float2 w1 = *(const float2*)&Wb1[j * 64 + c0];
#pragma unroll
        for (int u = 0; u < 4; u++) {
            int ln = slot * 4 + u;
            float a  = As[ln * 64 + j];
            float ax = Av[(ln * 3 + 0) * 64 + j];
            float ay = Av[(ln * 3 + 1) * 64 + j];
            float az = Av[(ln * 3 + 2) * 64 + j];
            aS[u][0] = fmaf(a,  w0.x, aS[u][0]); aS[u][1] = fmaf(a,  w0.y, aS[u][1]);
            aX[u][0] = fmaf(ax, w1.x, aX[u][0]); aX[u][1] = fmaf(ax, w1.y, aX[u][1]);
            aY[u][0] = fmaf(ay, w1.x, aY[u][0]); aY[u][1] = fmaf(ay, w1.y, aY[u][1]);
            aZ[u][0] = fmaf(az, w1.x, aZ[u][0]); aZ[u][1] = fmaf(az, w1.y, aZ[u][1]);
        }
    }

    if (LAYER < LL - 1) {
#pragma unroll
        for (int u = 0; u < 4; u++) {
            int n = nb + u;
            *(float2*)&sNew[n * 64 + c0] = make_float2(aS[u][0], aS[u][1]);
            *(float2*)&vNew[(n * 3 + 0) * 64 + c0] = make_float2(aX[u][0], aX[u][1]);
            *(float2*)&vNew[(n * 3 + 1) * 64 + c0] = make_float2(aY[u][0], aY[u][1]);
            *(float2*)&vNew[(n * 3 + 2) * 64 + c0] = make_float2(aZ[u][0], aZ[u][1]);
        }
    }

    if (LAYER == 0) {
        // linear readout: per-node partial over this thread's 2 channels,
        // warp reduce over 32 lanes (one slot's 4 nodes per warp)
        float w0 = Wread0[c0], w1 = Wread0[c0 + 1];
#pragma unroll
        for (int u = 0; u < 4; u++) {
            float part = aS[u][0] * w0 + aS[u][1] * w1;
#pragma unroll
            for (int o = 16; o > 0; o >>= 1)
                part += __shfl_xor_sync(0xffffffffu, part, o);
            if (fi == 0) out[(nb + u) * LL + 0] = part;
        }
    } else {
        // stage sN (reuse Bs), then MLP readout: 16 h-lanes per node, 2 passes
        __syncthreads();
#pragma unroll
        for (int u = 0; u < 4; u++)
            *(float2*)&Bs[(slot * 4 + u) * 64 + c0] = make_float2(aS[u][0], aS[u][1]);
        __syncthreads();
#pragma unroll
        for (int it = 0; it < 2; it++) {
            int ln2 = (t >> 4) + 16 * it;       // 0..31
            int h   = t & 15;
            float a = 0.f;
#pragma unroll 8
            for (int g = 0; g < FF; g++)
                a = fmaf(Bs[ln2 * 64 + g], Wr1a[g * HH + h], a);
            float sil = a / (1.f + __expf(-a));
            float part = sil * Wr1b[h];
#pragma unroll
            for (int o = 8; o > 0; o >>= 1)
                part += __shfl_xor_sync(0xffffffffu, part, o);
            if (h == 0) out[(blockIdx.x * 32 + ln2) * LL + (LL - 1)] = part;
        }
    }
}

// ---------------------------------------------------------------------------
extern "C" void kernel_launch(void* const* d_in, const int* in_sizes, int n_in,
                              void* d_out, int out_size) {
    const float* vectors = (const float*)d_in[0];
    const float* embed_s = (const float*)d_in[1];
    const float* Wr      = (const float*)d_in[2];
    const float* Wls     = (const float*)d_in[3];
    const float* Wlv     = (const float*)d_in[4];
    const float* skip_s  = (const float*)d_in[5];
    const float* skip_v  = (const float*)d_in[6];
    const float* pw      = (const float*)d_in[7];
    const float* Wps     = (const float*)d_in[8];
    const float* Wpv     = (const float*)d_in[9];
    const float* Wread0  = (const float*)d_in[10];
    const float* Wr1a    = (const float*)d_in[11];
    const float* Wr1b    = (const float*)d_in[12];
    const int*   senders   = (const int*)d_in[13];
    const int*   receivers = (const int*)d_in[14];
    const int*   species   = (const int*)d_in[15];
    float* out = (float*)d_out;

    void *p_sA, *p_vA, *p_sB, *p_vB;
    cudaGetSymbolAddress(&p_sA, g_sA);
    cudaGetSymbolAddress(&p_vA, g_vA);
    cudaGetSymbolAddress(&p_sB, g_sB);
    cudaGetSymbolAddress(&p_vB, g_vB);
    float* sA = (float*)p_sA;
    float* vA = (float*)p_vA;
    float* sB = (float*)p_sB;
    float* vB = (float*)p_vB;

    const int NODE0_SMEM = 16384 * 4;   // 64KB
    const int NODE1_SMEM = 24576 * 4;   // 96KB
    static bool attrSet = false;
    if (!attrSet) {
        cudaFuncSetAttribute(nodeK<0>, cudaFuncAttributeMaxDynamicSharedMemorySize, NODE0_SMEM);
        cudaFuncSetAttribute(nodeK<1>, cudaFuncAttributeMaxDynamicSharedMemorySize, NODE1_SMEM);
        attrSet = true;
    }

    initK<<<(NN * FF / 4 + 255) / 256, 256>>>(embed_s, species);

    // ---- Layer 0 ----
    edgeK<true><<<EE / 128, 256>>>(vectors, Wr, senders, receivers, sA, vA);
    nodeK<0><<<NN / 32, 256, NODE0_SMEM>>>(sA, vA, sB, vB, species,
                              Wls, Wlv, pw, Wps, Wpv,
                              skip_s, skip_v, Wread0, Wr1a, Wr1b, out);

    // ---- Layer 1 ----
    edgeK<false><<<EE / 128, 256>>>(vectors, Wr + NBB * 5 * FF, senders, receivers, sB, vB);
    nodeK<1><<<NN / 32, 256, NODE1_SMEM>>>(sB, vB, sA, vA, species,
                              Wls + FF * FF, Wlv + FF * FF,
                              pw + ZZ * 9 * FF,
                              Wps + FF * FF, Wpv + FF * FF,
                              skip_s, skip_v, Wread0, Wr1a, Wr1b, out);
}